// round 9
// baseline (speedup 1.0000x reference)
#include <cuda_runtime.h>
#include <cuda_bf16.h>
#include <stdint.h>
#include <float.h>

#define N_ROWS   32768
#define K_CODES  8192
#define DIM      64
#define TH       256
#define ROWS_CTA 128            // 8 warps x 16 rows
#define NCH      64             // codes per staged chunk
#define NCHUNKS  (K_CODES / NCH)
#define CSTRIDE  272            // bytes per code row in smem (256 + 16 pad)
#define BUFB     (NCH * CSTRIDE)
#define TAU      0.0625f        // hard bound on |dist error| of the 3-term bf16 path

// ---------------- device globals (no allocation allowed) ----------------
__device__ unsigned g_cpack[K_CODES * 64];  // per code: 8 groups x [q,q+4 interleaved] pairs
__device__ float    g_csq[K_CODES];
__device__ int      g_fixcount;
__device__ int      g_fixlist[N_ROWS];

// ---------------- small helpers ----------------
__device__ __forceinline__ void split2(float a, float b, unsigned& hi, unsigned& lo) {
    __nv_bfloat16 ha = __float2bfloat16_rn(a), hb = __float2bfloat16_rn(b);
    float ra = a - __bfloat162float(ha), rb = b - __bfloat162float(hb);
    __nv_bfloat162 h, l;
    h.x = ha; h.y = hb;
    l.x = __float2bfloat16_rn(ra); l.y = __float2bfloat16_rn(rb);
    hi = *reinterpret_cast<unsigned*>(&h);
    lo = *reinterpret_cast<unsigned*>(&l);
}
__device__ __forceinline__ uint32_t smem_u32(const void* p) {
    uint32_t a;
    asm("{ .reg .u64 t; cvta.to.shared.u64 t, %1; cvt.u32.u64 %0, t; }" : "=r"(a) : "l"(p));
    return a;
}
__device__ __forceinline__ void cp16(uint32_t dst, const void* src) {
    asm volatile("cp.async.ca.shared.global [%0], [%1], 16;" :: "r"(dst), "l"(src) : "memory");
}
#define CP_COMMIT() asm volatile("cp.async.commit_group;" ::: "memory")
#define CP_WAIT1()  asm volatile("cp.async.wait_group 1;" ::: "memory")
#define CP_WAIT0()  asm volatile("cp.async.wait_group 0;" ::: "memory")

__device__ __forceinline__ void mma16816(float& c0, float& c1, float& c2, float& c3,
                                         unsigned a0, unsigned a1, unsigned a2, unsigned a3,
                                         unsigned b0, unsigned b1) {
    asm volatile(
        "mma.sync.aligned.m16n8k16.row.col.f32.bf16.bf16.f32 "
        "{%0,%1,%2,%3}, {%4,%5,%6,%7}, {%8,%9}, {%0,%1,%2,%3};"
        : "+f"(c0), "+f"(c1), "+f"(c2), "+f"(c3)
        : "r"(a0), "r"(a1), "r"(a2), "r"(a3), "r"(b0), "r"(b1));
}
__device__ __forceinline__ void lds_v2(unsigned& x, unsigned& y, uint32_t addr) {
    asm volatile("ld.shared.v2.b32 {%0,%1}, [%2];" : "=r"(x), "=r"(y) : "r"(addr));
}

// ---------------- prologue: pack codebook (coalesced), csq, reset ----------------
// thread <-> (code, group): 65536 threads, 256 blocks.
__global__ void pack_cb_kernel(const float* __restrict__ cb) {
    int idx = blockIdx.x * blockDim.x + threadIdx.x;
    if (idx == 0) g_fixcount = 0;
    if (idx >= K_CODES * 8) return;
    int code = idx >> 3, g = idx & 7;
    int db = 16 * (g & 3);                    // dim base of this 16-dim kstep
    bool want_hi = (g < 4);

    float f[16];
    const float4* cp4 = reinterpret_cast<const float4*>(cb + (size_t)code * DIM + db);
#pragma unroll
    for (int i = 0; i < 4; i++) *reinterpret_cast<float4*>(f + 4 * i) = cp4[i];

    unsigned r[8];
#pragma unroll
    for (int m = 0; m < 4; m++) {
#pragma unroll
        for (int h = 0; h < 2; h++) {
            int q = m + 4 * h;
            unsigned hi, lo;
            split2(f[2 * q], f[2 * q + 1], hi, lo);
            r[2 * m + h] = want_hi ? hi : lo;
        }
    }
    uint4* dst = reinterpret_cast<uint4*>(g_cpack + (size_t)code * 64 + g * 8);
    dst[0] = *reinterpret_cast<uint4*>(r);
    dst[1] = *reinterpret_cast<uint4*>(r + 4);

    if (g == 0) {
        const float4* c4 = reinterpret_cast<const float4*>(cb + (size_t)code * DIM);
        float s = 0.f;
#pragma unroll
        for (int i = 0; i < 16; i++) {
            float4 v = c4[i];
            s = fmaf(v.x, v.x, s); s = fmaf(v.y, v.y, s);
            s = fmaf(v.z, v.z, s); s = fmaf(v.w, v.w, s);
        }
        g_csq[code] = s;
    }
}

// ---------------- main GEMM-argmin kernel ----------------
__global__ __launch_bounds__(TH, 2)
void vq_mma_kernel(const float* __restrict__ x, float* __restrict__ out) {
    __shared__ char bsm[2 * BUFB];     // 34816 B, double-buffered B chunks
    const uint32_t sb = smem_u32(bsm);

    const int tid  = threadIdx.x;
    const int lane = tid & 31;
    const int wid  = tid >> 5;
    const int m    = lane & 3;         // quad lane
    const int r4   = lane >> 2;        // 0..7
    const int r0   = blockIdx.x * ROWS_CTA + wid * 16;
    const int rowA = r0 + r4, rowB = rowA + 8;

    // ---- A fragments built in-kernel: u<4 = hi ksteps, u>=4 = lo ksteps ----
    unsigned a[8][4];
    {
        const float2* x2 = reinterpret_cast<const float2*>(x);
#pragma unroll
        for (int u = 0; u < 4; u++) {
            int p1 = 8 * u + m, p2 = p1 + 4;
            float2 vA1 = __ldg(x2 + (size_t)rowA * 32 + p1);
            float2 vB1 = __ldg(x2 + (size_t)rowB * 32 + p1);
            float2 vA2 = __ldg(x2 + (size_t)rowA * 32 + p2);
            float2 vB2 = __ldg(x2 + (size_t)rowB * 32 + p2);
            split2(vA1.x, vA1.y, a[u][0], a[u + 4][0]);
            split2(vB1.x, vB1.y, a[u][1], a[u + 4][1]);
            split2(vA2.x, vA2.y, a[u][2], a[u + 4][2]);
            split2(vB2.x, vB2.y, a[u][3], a[u + 4][3]);
        }
    }

    float v1[2] = {FLT_MAX, FLT_MAX};  // best dist (rowA, rowB)
    float v2[2] = {FLT_MAX, FLT_MAX};  // second-best
    int   i1[2] = {0, 0};

    // ---- stage chunk 0 ----
#pragma unroll
    for (int t = 0; t < 4; t++) {
        int gid = t * TH + tid;                  // 1024 granules
        int c = gid >> 4, g = gid & 15;
        cp16(sb + c * CSTRIDE + g * 16, g_cpack + (size_t)c * 64 + g * 4);
    }
    CP_COMMIT();

    for (int ch = 0; ch < NCHUNKS; ch++) {
        const int s = ch & 1;
        if (ch) __syncthreads();                 // all done reading buf[s^1]
        if (ch + 1 < NCHUNKS) {
#pragma unroll
            for (int t = 0; t < 4; t++) {
                int gid = t * TH + tid;
                int c = gid >> 4, g = gid & 15;
                cp16(sb + (s ^ 1) * BUFB + c * CSTRIDE + g * 16,
                     g_cpack + ((size_t)(ch + 1) * NCH + c) * 64 + g * 4);
            }
            CP_COMMIT();
            CP_WAIT1();
        } else {
            CP_WAIT0();
        }
        __syncthreads();                         // chunk ch visible to all warps

        const uint32_t bufs = sb + s * BUFB;
#pragma unroll
        for (int sub = 0; sub < 8; sub++) {      // 8 n8-tiles per chunk
            const int n0 = ch * NCH + sub * 8;
            const uint32_t crow = bufs + (sub * 8 + r4) * CSTRIDE;

            float2 cq = __ldg(reinterpret_cast<const float2*>(g_csq + n0 + 2 * m));

            unsigned bg[8], bh[8];
#pragma unroll
            for (int g = 0; g < 4; g++) lds_v2(bg[2 * g], bg[2 * g + 1], crow + g * 32 + m * 8);
#pragma unroll
            for (int g = 0; g < 4; g++) lds_v2(bh[2 * g], bh[2 * g + 1], crow + (4 + g) * 32 + m * 8);

            // 3 independent 4-deep accumulator chains -> tensor-pipe ILP
            float p0 = 0.f, p1_ = 0.f, p2_ = 0.f, p3 = 0.f;   // hi_x * hi_c
            float q0 = 0.f, q1 = 0.f, q2 = 0.f, q3 = 0.f;     // lo_x * hi_c
            float e0 = 0.f, e1 = 0.f, e2 = 0.f, e3 = 0.f;     // hi_x * lo_c
#pragma unroll
            for (int k = 0; k < 4; k++) {
                mma16816(p0, p1_, p2_, p3, a[k][0], a[k][1], a[k][2], a[k][3], bg[2 * k], bg[2 * k + 1]);
                mma16816(q0, q1, q2, q3, a[4 + k][0], a[4 + k][1], a[4 + k][2], a[4 + k][3], bg[2 * k], bg[2 * k + 1]);
                mma16816(e0, e1, e2, e3, a[k][0], a[k][1], a[k][2], a[k][3], bh[2 * k], bh[2 * k + 1]);
            }
            float c0 = p0 + q0 + e0, c1 = p1_ + q1 + e1;
            float c2 = p2_ + q2 + e2, c3 = p3 + q3 + e3;

            // dists; within-lane sequential ascending index => first-min kept
            const int jA = n0 + 2 * m, jB = jA + 1;
            float d;
            d = fmaf(-2.f, c0, cq.x);
            if (d < v1[0]) { v2[0] = v1[0]; v1[0] = d; i1[0] = jA; } else if (d < v2[0]) v2[0] = d;
            d = fmaf(-2.f, c1, cq.y);
            if (d < v1[0]) { v2[0] = v1[0]; v1[0] = d; i1[0] = jB; } else if (d < v2[0]) v2[0] = d;
            d = fmaf(-2.f, c2, cq.x);
            if (d < v1[1]) { v2[1] = v1[1]; v1[1] = d; i1[1] = jA; } else if (d < v2[1]) v2[1] = d;
            d = fmaf(-2.f, c3, cq.y);
            if (d < v1[1]) { v2[1] = v1[1]; v1[1] = d; i1[1] = jB; } else if (d < v2[1]) v2[1] = d;
        }
    }

    // ---- merge the 4 quad lanes (lexicographic => global first-min) ----
#pragma unroll
    for (int dmask = 1; dmask < 4; dmask <<= 1) {
#pragma unroll
        for (int i = 0; i < 2; i++) {
            float ov1 = __shfl_xor_sync(0xffffffffu, v1[i], dmask);
            int   oi1 = __shfl_xor_sync(0xffffffffu, i1[i], dmask);
            float ov2 = __shfl_xor_sync(0xffffffffu, v2[i], dmask);
            if (ov1 < v1[i] || (ov1 == v1[i] && oi1 < i1[i])) {
                v2[i] = fminf(v1[i], ov2);
                v1[i] = ov1; i1[i] = oi1;
            } else {
                v2[i] = fminf(v2[i], ov1);
            }
        }
    }
    if (m == 0) {
        out[rowA] = (float)i1[0];
        out[rowB] = (float)i1[1];
        if (v2[0] - v1[0] < TAU) { int k = atomicAdd(&g_fixcount, 1); g_fixlist[k] = rowA; }
        if (v2[1] - v1[1] < TAU) { int k = atomicAdd(&g_fixcount, 1); g_fixlist[k] = rowB; }
    }
}

// ---------------- exact fp32 fixup for near-tie rows ----------------
__global__ void fixup_kernel(const float* __restrict__ x,
                             const float* __restrict__ cb,
                             float* __restrict__ out) {
    __shared__ float xr[DIM];
    __shared__ float sv[TH];
    __shared__ int   si[TH];
    const int tid = threadIdx.x;
    const int nfix = g_fixcount;

    for (int fi = blockIdx.x; fi < nfix; fi += gridDim.x) {
        int row = g_fixlist[fi];
        __syncthreads();
        if (tid < DIM) xr[tid] = x[(size_t)row * DIM + tid];
        __syncthreads();

        float bv = FLT_MAX; int bi = 0;
        for (int j = tid; j < K_CODES; j += 2 * TH) {
            const float* ca = cb + (size_t)j * DIM;
            const float* cbp = cb + (size_t)(j + TH) * DIM;
            float da = 0.f, db_ = 0.f;           // two independent chains
#pragma unroll
            for (int d = 0; d < DIM; d++) {
                da  = fmaf(xr[d], ca[d], da);
                db_ = fmaf(xr[d], cbp[d], db_);
            }
            float dista = fmaf(-2.f, da, g_csq[j]);
            float distb = fmaf(-2.f, db_, g_csq[j + TH]);
            if (dista < bv) { bv = dista; bi = j; }
            if (distb < bv) { bv = distb; bi = j + TH; }
        }
        sv[tid] = bv; si[tid] = bi;
        __syncthreads();
        for (int st = TH / 2; st > 0; st >>= 1) {
            if (tid < st) {
                float ov = sv[tid + st]; int oi = si[tid + st];
                if (ov < sv[tid] || (ov == sv[tid] && oi < si[tid])) { sv[tid] = ov; si[tid] = oi; }
            }
            __syncthreads();
        }
        if (tid == 0) out[row] = (float)si[0];
        __syncthreads();
    }
}

extern "C" void kernel_launch(void* const* d_in, const int* in_sizes, int n_in,
                              void* d_out, int out_size) {
    const float* x  = (const float*)d_in[0];
    const float* cb = (const float*)d_in[1];
    if (n_in >= 2 && in_sizes[0] == K_CODES * DIM && in_sizes[1] == N_ROWS * DIM) {
        const float* t = x; x = cb; cb = t;
    }
    float* out = (float*)d_out;

    pack_cb_kernel<<<(K_CODES * 8) / TH, TH>>>(cb);
    vq_mma_kernel<<<N_ROWS / ROWS_CTA, TH>>>(x, out);
    fixup_kernel<<<256, TH>>>(x, cb, out);
}

// round 10
// speedup vs baseline: 1.0014x; 1.0014x over previous
#include <cuda_runtime.h>
#include <cuda_bf16.h>
#include <stdint.h>
#include <float.h>

#define N_ROWS   32768
#define K_CODES  8192
#define DIM      64
#define TH       256
#define ROWS_CTA 128            // 8 warps x 16 rows
#define NCH      64             // codes per staged chunk
#define NCHUNKS  (K_CODES / NCH)
#define CSTRIDE  272            // bytes per code row in smem (256 + 16 pad)
#define BUFB     (NCH * CSTRIDE)
#define TAU      0.0625f        // hard bound on |dist error| of the 3-term bf16 path

// ---------------- device globals (no allocation allowed) ----------------
__device__ unsigned g_cpack[K_CODES * 64];  // per code: 8 groups x [q,q+4 interleaved] pairs
__device__ float    g_csq[K_CODES];
__device__ int      g_fixcount;
__device__ int      g_fixlist[N_ROWS];

// ---------------- small helpers ----------------
__device__ __forceinline__ void split2(float a, float b, unsigned& hi, unsigned& lo) {
    __nv_bfloat16 ha = __float2bfloat16_rn(a), hb = __float2bfloat16_rn(b);
    float ra = a - __bfloat162float(ha), rb = b - __bfloat162float(hb);
    __nv_bfloat162 h, l;
    h.x = ha; h.y = hb;
    l.x = __float2bfloat16_rn(ra); l.y = __float2bfloat16_rn(rb);
    hi = *reinterpret_cast<unsigned*>(&h);
    lo = *reinterpret_cast<unsigned*>(&l);
}
__device__ __forceinline__ uint32_t smem_u32(const void* p) {
    uint32_t a;
    asm("{ .reg .u64 t; cvta.to.shared.u64 t, %1; cvt.u32.u64 %0, t; }" : "=r"(a) : "l"(p));
    return a;
}
__device__ __forceinline__ void cp16(uint32_t dst, const void* src) {
    asm volatile("cp.async.ca.shared.global [%0], [%1], 16;" :: "r"(dst), "l"(src) : "memory");
}
#define CP_COMMIT() asm volatile("cp.async.commit_group;" ::: "memory")
#define CP_WAIT1()  asm volatile("cp.async.wait_group 1;" ::: "memory")
#define CP_WAIT0()  asm volatile("cp.async.wait_group 0;" ::: "memory")

__device__ __forceinline__ void mma16816(float& c0, float& c1, float& c2, float& c3,
                                         unsigned a0, unsigned a1, unsigned a2, unsigned a3,
                                         unsigned b0, unsigned b1) {
    asm volatile(
        "mma.sync.aligned.m16n8k16.row.col.f32.bf16.bf16.f32 "
        "{%0,%1,%2,%3}, {%4,%5,%6,%7}, {%8,%9}, {%0,%1,%2,%3};"
        : "+f"(c0), "+f"(c1), "+f"(c2), "+f"(c3)
        : "r"(a0), "r"(a1), "r"(a2), "r"(a3), "r"(b0), "r"(b1));
}
__device__ __forceinline__ void lds_v2(unsigned& x, unsigned& y, uint32_t addr) {
    asm volatile("ld.shared.v2.b32 {%0,%1}, [%2];" : "=r"(x), "=r"(y) : "r"(addr));
}

// ---------------- prologue: pack codebook (coalesced), csq, reset ----------------
// thread <-> (code, group): 65536 threads, 256 blocks.
__global__ void pack_cb_kernel(const float* __restrict__ cb) {
    int idx = blockIdx.x * blockDim.x + threadIdx.x;
    if (idx == 0) g_fixcount = 0;
    if (idx >= K_CODES * 8) return;
    int code = idx >> 3, g = idx & 7;
    int db = 16 * (g & 3);                    // dim base of this 16-dim kstep
    bool want_hi = (g < 4);

    float f[16];
    const float4* cp4 = reinterpret_cast<const float4*>(cb + (size_t)code * DIM + db);
#pragma unroll
    for (int i = 0; i < 4; i++) *reinterpret_cast<float4*>(f + 4 * i) = cp4[i];

    unsigned r[8];
#pragma unroll
    for (int m = 0; m < 4; m++) {
#pragma unroll
        for (int h = 0; h < 2; h++) {
            int q = m + 4 * h;
            unsigned hi, lo;
            split2(f[2 * q], f[2 * q + 1], hi, lo);
            r[2 * m + h] = want_hi ? hi : lo;
        }
    }
    uint4* dst = reinterpret_cast<uint4*>(g_cpack + (size_t)code * 64 + g * 8);
    dst[0] = *reinterpret_cast<uint4*>(r);
    dst[1] = *reinterpret_cast<uint4*>(r + 4);

    if (g == 0) {
        const float4* c4 = reinterpret_cast<const float4*>(cb + (size_t)code * DIM);
        float s = 0.f;
#pragma unroll
        for (int i = 0; i < 16; i++) {
            float4 v = c4[i];
            s = fmaf(v.x, v.x, s); s = fmaf(v.y, v.y, s);
            s = fmaf(v.z, v.z, s); s = fmaf(v.w, v.w, s);
        }
        g_csq[code] = s;
    }
}

// ---------------- main GEMM-argmin kernel ----------------
__global__ __launch_bounds__(TH, 2)
void vq_mma_kernel(const float* __restrict__ x, float* __restrict__ out) {
    __shared__ char bsm[2 * BUFB];     // 34816 B, double-buffered B chunks
    const uint32_t sb = smem_u32(bsm);

    const int tid  = threadIdx.x;
    const int lane = tid & 31;
    const int wid  = tid >> 5;
    const int m    = lane & 3;         // quad lane
    const int r4   = lane >> 2;        // 0..7
    const int r0   = blockIdx.x * ROWS_CTA + wid * 16;
    const int rowA = r0 + r4, rowB = rowA + 8;

    // ---- A fragments built in-kernel: u<4 = hi ksteps, u>=4 = lo ksteps ----
    unsigned a[8][4];
    {
        const float2* x2 = reinterpret_cast<const float2*>(x);
#pragma unroll
        for (int u = 0; u < 4; u++) {
            int p1 = 8 * u + m, p2 = p1 + 4;
            float2 vA1 = __ldg(x2 + (size_t)rowA * 32 + p1);
            float2 vB1 = __ldg(x2 + (size_t)rowB * 32 + p1);
            float2 vA2 = __ldg(x2 + (size_t)rowA * 32 + p2);
            float2 vB2 = __ldg(x2 + (size_t)rowB * 32 + p2);
            split2(vA1.x, vA1.y, a[u][0], a[u + 4][0]);
            split2(vB1.x, vB1.y, a[u][1], a[u + 4][1]);
            split2(vA2.x, vA2.y, a[u][2], a[u + 4][2]);
            split2(vB2.x, vB2.y, a[u][3], a[u + 4][3]);
        }
    }

    float v1[2] = {FLT_MAX, FLT_MAX};  // best dist (rowA, rowB)
    float v2[2] = {FLT_MAX, FLT_MAX};  // second-best
    int   i1[2] = {0, 0};

    // ---- stage chunk 0 ----
#pragma unroll
    for (int t = 0; t < 4; t++) {
        int gid = t * TH + tid;                  // 1024 granules
        int c = gid >> 4, g = gid & 15;
        cp16(sb + c * CSTRIDE + g * 16, g_cpack + (size_t)c * 64 + g * 4);
    }
    CP_COMMIT();

    for (int ch = 0; ch < NCHUNKS; ch++) {
        const int s = ch & 1;
        if (ch) __syncthreads();                 // all done reading buf[s^1]
        if (ch + 1 < NCHUNKS) {
#pragma unroll
            for (int t = 0; t < 4; t++) {
                int gid = t * TH + tid;
                int c = gid >> 4, g = gid & 15;
                cp16(sb + (s ^ 1) * BUFB + c * CSTRIDE + g * 16,
                     g_cpack + ((size_t)(ch + 1) * NCH + c) * 64 + g * 4);
            }
            CP_COMMIT();
            CP_WAIT1();
        } else {
            CP_WAIT0();
        }
        __syncthreads();                         // chunk ch visible to all warps

        const uint32_t bufs = sb + s * BUFB;
#pragma unroll
        for (int sub = 0; sub < 8; sub++) {      // 8 n8-tiles per chunk
            const int n0 = ch * NCH + sub * 8;
            const uint32_t crow = bufs + (sub * 8 + r4) * CSTRIDE;

            float2 cq = __ldg(reinterpret_cast<const float2*>(g_csq + n0 + 2 * m));

            unsigned bg[8], bh[8];
#pragma unroll
            for (int g = 0; g < 4; g++) lds_v2(bg[2 * g], bg[2 * g + 1], crow + g * 32 + m * 8);
#pragma unroll
            for (int g = 0; g < 4; g++) lds_v2(bh[2 * g], bh[2 * g + 1], crow + (4 + g) * 32 + m * 8);

            // 3 independent 4-deep accumulator chains -> tensor-pipe ILP
            float p0 = 0.f, p1_ = 0.f, p2_ = 0.f, p3 = 0.f;   // hi_x * hi_c
            float q0 = 0.f, q1 = 0.f, q2 = 0.f, q3 = 0.f;     // lo_x * hi_c
            float e0 = 0.f, e1 = 0.f, e2 = 0.f, e3 = 0.f;     // hi_x * lo_c
#pragma unroll
            for (int k = 0; k < 4; k++) {
                mma16816(p0, p1_, p2_, p3, a[k][0], a[k][1], a[k][2], a[k][3], bg[2 * k], bg[2 * k + 1]);
                mma16816(q0, q1, q2, q3, a[4 + k][0], a[4 + k][1], a[4 + k][2], a[4 + k][3], bg[2 * k], bg[2 * k + 1]);
                mma16816(e0, e1, e2, e3, a[k][0], a[k][1], a[k][2], a[k][3], bh[2 * k], bh[2 * k + 1]);
            }
            float c0 = p0 + q0 + e0, c1 = p1_ + q1 + e1;
            float c2 = p2_ + q2 + e2, c3 = p3 + q3 + e3;

            // dists; within-lane sequential ascending index => first-min kept
            const int jA = n0 + 2 * m, jB = jA + 1;
            float d;
            d = fmaf(-2.f, c0, cq.x);
            if (d < v1[0]) { v2[0] = v1[0]; v1[0] = d; i1[0] = jA; } else if (d < v2[0]) v2[0] = d;
            d = fmaf(-2.f, c1, cq.y);
            if (d < v1[0]) { v2[0] = v1[0]; v1[0] = d; i1[0] = jB; } else if (d < v2[0]) v2[0] = d;
            d = fmaf(-2.f, c2, cq.x);
            if (d < v1[1]) { v2[1] = v1[1]; v1[1] = d; i1[1] = jA; } else if (d < v2[1]) v2[1] = d;
            d = fmaf(-2.f, c3, cq.y);
            if (d < v1[1]) { v2[1] = v1[1]; v1[1] = d; i1[1] = jB; } else if (d < v2[1]) v2[1] = d;
        }
    }

    // ---- merge the 4 quad lanes (lexicographic => global first-min) ----
#pragma unroll
    for (int dmask = 1; dmask < 4; dmask <<= 1) {
#pragma unroll
        for (int i = 0; i < 2; i++) {
            float ov1 = __shfl_xor_sync(0xffffffffu, v1[i], dmask);
            int   oi1 = __shfl_xor_sync(0xffffffffu, i1[i], dmask);
            float ov2 = __shfl_xor_sync(0xffffffffu, v2[i], dmask);
            if (ov1 < v1[i] || (ov1 == v1[i] && oi1 < i1[i])) {
                v2[i] = fminf(v1[i], ov2);
                v1[i] = ov1; i1[i] = oi1;
            } else {
                v2[i] = fminf(v2[i], ov1);
            }
        }
    }
    if (m == 0) {
        out[rowA] = (float)i1[0];
        out[rowB] = (float)i1[1];
        if (v2[0] - v1[0] < TAU) { int k = atomicAdd(&g_fixcount, 1); g_fixlist[k] = rowA; }
        if (v2[1] - v1[1] < TAU) { int k = atomicAdd(&g_fixcount, 1); g_fixlist[k] = rowB; }
    }
}

// ---------------- exact fp32 fixup for near-tie rows ----------------
__global__ void fixup_kernel(const float* __restrict__ x,
                             const float* __restrict__ cb,
                             float* __restrict__ out) {
    __shared__ float xr[DIM];
    __shared__ float sv[TH];
    __shared__ int   si[TH];
    const int tid = threadIdx.x;
    const int nfix = g_fixcount;

    for (int fi = blockIdx.x; fi < nfix; fi += gridDim.x) {
        int row = g_fixlist[fi];
        __syncthreads();
        if (tid < DIM) xr[tid] = x[(size_t)row * DIM + tid];
        __syncthreads();

        float bv = FLT_MAX; int bi = 0;
        for (int j = tid; j < K_CODES; j += 2 * TH) {
            const float* ca = cb + (size_t)j * DIM;
            const float* cbp = cb + (size_t)(j + TH) * DIM;
            float da = 0.f, db_ = 0.f;           // two independent chains
#pragma unroll
            for (int d = 0; d < DIM; d++) {
                da  = fmaf(xr[d], ca[d], da);
                db_ = fmaf(xr[d], cbp[d], db_);
            }
            float dista = fmaf(-2.f, da, g_csq[j]);
            float distb = fmaf(-2.f, db_, g_csq[j + TH]);
            if (dista < bv) { bv = dista; bi = j; }
            if (distb < bv) { bv = distb; bi = j + TH; }
        }
        sv[tid] = bv; si[tid] = bi;
        __syncthreads();
        for (int st = TH / 2; st > 0; st >>= 1) {
            if (tid < st) {
                float ov = sv[tid + st]; int oi = si[tid + st];
                if (ov < sv[tid] || (ov == sv[tid] && oi < si[tid])) { sv[tid] = ov; si[tid] = oi; }
            }
            __syncthreads();
        }
        if (tid == 0) out[row] = (float)si[0];
        __syncthreads();
    }
}

extern "C" void kernel_launch(void* const* d_in, const int* in_sizes, int n_in,
                              void* d_out, int out_size) {
    const float* x  = (const float*)d_in[0];
    const float* cb = (const float*)d_in[1];
    if (n_in >= 2 && in_sizes[0] == K_CODES * DIM && in_sizes[1] == N_ROWS * DIM) {
        const float* t = x; x = cb; cb = t;
    }
    float* out = (float*)d_out;

    pack_cb_kernel<<<(K_CODES * 8) / TH, TH>>>(cb);
    vq_mma_kernel<<<N_ROWS / ROWS_CTA, TH>>>(x, out);
    fixup_kernel<<<256, TH>>>(x, cb, out);
}